// round 1
// baseline (speedup 1.0000x reference)
#include <cuda_runtime.h>
#include <math.h>

#define BATCH 8
#define DIM   128
#define NSEQ  2048
#define BM    64          // m-tile (K/output columns) per block
#define BN    64          // n-tile (Q columns / reduction dim of PV)
#define LDS_  68          // padded smem leading dim (floats), multiple of 4

// smem: Ks[128][68] + Qc[32][68] + Vs[128][68] + Ps[64][68]
#define SMEM_FLOATS ((DIM + 32 + DIM + BN) * LDS_)
#define SMEM_BYTES  (SMEM_FLOATS * 4)

__global__ __launch_bounds__(256, 2)
void sigattn_kernel(const float* __restrict__ Q, const float* __restrict__ K,
                    const float* __restrict__ V, float* __restrict__ O) {
    extern __shared__ float sm[];
    float* Ks = sm;                     // [128][LDS_]  K tile, resident whole block
    float* Qc = Ks + DIM * LDS_;        // [32][LDS_]   Q d-chunk
    float* Vs = Qc + 32  * LDS_;        // [128][LDS_]  V tile
    float* Ps = Vs + DIM * LDS_;        // [64][LDS_]   sigmoid scores

    const int b  = blockIdx.y;
    const int m0 = blockIdx.x * BM;
    const float* Qb = Q + (size_t)b * DIM * NSEQ;
    const float* Kb = K + (size_t)b * DIM * NSEQ;
    const float* Vb = V + (size_t)b * DIM * NSEQ;
    float*       Ob = O + (size_t)b * DIM * NSEQ;

    const int tid = threadIdx.x;
    const int tm  = tid & 15;   // 0..15 : m microtile index
    const int tn  = tid >> 4;   // 0..15 : n microtile (phase1) / v microtile (phase2)

    // ---- Load K tile once: Ks[d][j] = K[b][d][m0+j] ----
    for (int i = tid; i < DIM * (BM / 4); i += 256) {
        int d  = i >> 4;            // BM/4 = 16 float4 per row
        int j4 = (i & 15) << 2;
        float4 v = *(const float4*)(Kb + (size_t)d * NSEQ + m0 + j4);
        *(float4*)(&Ks[d * LDS_ + j4]) = v;
    }

    float acc[8][4];
#pragma unroll
    for (int i = 0; i < 8; i++)
#pragma unroll
        for (int j = 0; j < 4; j++) acc[i][j] = 0.0f;

    const float scale = 0.08838834764831845f;  // 1/sqrt(128)

    for (int n0 = 0; n0 < NSEQ; n0 += BN) {
        // ---------- Phase 1: S[n,m] = sum_d Q[d,n]*K[d,m] ----------
        float s[4][4];
#pragma unroll
        for (int i = 0; i < 4; i++)
#pragma unroll
            for (int j = 0; j < 4; j++) s[i][j] = 0.0f;

        for (int dc = 0; dc < DIM; dc += 32) {
            __syncthreads();  // protect Qc reuse (and phase-2 reads of prev iter)
            for (int i = tid; i < 32 * 16; i += 256) {
                int dr = i >> 4;
                int j4 = (i & 15) << 2;
                *(float4*)(&Qc[dr * LDS_ + j4]) =
                    *(const float4*)(Qb + (size_t)(dc + dr) * NSEQ + n0 + j4);
            }
            __syncthreads();
#pragma unroll 8
            for (int d = 0; d < 32; d++) {
                float4 q = *(const float4*)(&Qc[d * LDS_ + tn * 4]);
                float4 k = *(const float4*)(&Ks[(dc + d) * LDS_ + tm * 4]);
                s[0][0] += q.x * k.x; s[0][1] += q.x * k.y; s[0][2] += q.x * k.z; s[0][3] += q.x * k.w;
                s[1][0] += q.y * k.x; s[1][1] += q.y * k.y; s[1][2] += q.y * k.z; s[1][3] += q.y * k.w;
                s[2][0] += q.z * k.x; s[2][1] += q.z * k.y; s[2][2] += q.z * k.z; s[2][3] += q.z * k.w;
                s[3][0] += q.w * k.x; s[3][1] += q.w * k.y; s[3][2] += q.w * k.z; s[3][3] += q.w * k.w;
            }
        }

        // ---------- sigmoid -> Ps, stream V tile ----------
#pragma unroll
        for (int i = 0; i < 4; i++) {
            float4 p;
            p.x = 1.0f / (1.0f + __expf(-s[i][0] * scale));
            p.y = 1.0f / (1.0f + __expf(-s[i][1] * scale));
            p.z = 1.0f / (1.0f + __expf(-s[i][2] * scale));
            p.w = 1.0f / (1.0f + __expf(-s[i][3] * scale));
            *(float4*)(&Ps[(tn * 4 + i) * LDS_ + tm * 4]) = p;
        }
        for (int i = tid; i < DIM * 16; i += 256) {
            int v  = i >> 4;
            int j4 = (i & 15) << 2;
            *(float4*)(&Vs[v * LDS_ + j4]) =
                *(const float4*)(Vb + (size_t)v * NSEQ + n0 + j4);
        }
        __syncthreads();

        // ---------- Phase 2: O[v,m] += sum_n V[v,n]*P[n,m] ----------
#pragma unroll 2
        for (int nn = 0; nn < BN; nn += 4) {
            float4 p0 = *(const float4*)(&Ps[(nn + 0) * LDS_ + tm * 4]);
            float4 p1 = *(const float4*)(&Ps[(nn + 1) * LDS_ + tm * 4]);
            float4 p2 = *(const float4*)(&Ps[(nn + 2) * LDS_ + tm * 4]);
            float4 p3 = *(const float4*)(&Ps[(nn + 3) * LDS_ + tm * 4]);
#pragma unroll
            for (int i = 0; i < 8; i++) {
                float4 va = *(const float4*)(&Vs[(tn * 8 + i) * LDS_ + nn]);
                acc[i][0] += va.x * p0.x + va.y * p1.x + va.z * p2.x + va.w * p3.x;
                acc[i][1] += va.x * p0.y + va.y * p1.y + va.z * p2.y + va.w * p3.y;
                acc[i][2] += va.x * p0.z + va.y * p1.z + va.z * p2.z + va.w * p3.z;
                acc[i][3] += va.x * p0.w + va.y * p1.w + va.z * p2.w + va.w * p3.w;
            }
        }
    }

    // ---- Write O[v][m0+..] ----
#pragma unroll
    for (int i = 0; i < 8; i++) {
        float4 o;
        o.x = acc[i][0]; o.y = acc[i][1]; o.z = acc[i][2]; o.w = acc[i][3];
        *(float4*)(Ob + (size_t)(tn * 8 + i) * NSEQ + m0 + tm * 4) = o;
    }
}

extern "C" void kernel_launch(void* const* d_in, const int* in_sizes, int n_in,
                              void* d_out, int out_size) {
    const float* Q = (const float*)d_in[0];
    const float* K = (const float*)d_in[1];
    const float* V = (const float*)d_in[2];
    float* O = (float*)d_out;

    cudaFuncSetAttribute(sigattn_kernel,
                         cudaFuncAttributeMaxDynamicSharedMemorySize, SMEM_BYTES);

    dim3 grid(NSEQ / BM, BATCH);
    sigattn_kernel<<<grid, 256, SMEM_BYTES>>>(Q, K, V, O);
}